// round 5
// baseline (speedup 1.0000x reference)
#include <cuda_runtime.h>
#include <math.h>

// CRF log-likelihood. N=2048, T=200, L=129, fp32, scalar output.
//
// Forward recurrence in normalized exp-domain:
//   s[j] = sum_i p[i] * E[i][j],  E = exp(transitions)   (precomputed)
//   u[j] = s[j] * exp(logit_t[j]);  renorm every 4 steps into c2 (log2 scale)
//   log_den = ln2 * (c2 + log2(sum_j p[j]*exp(end[j])))
//
// Matvec uses fp32x2 packed FMA (fma.rn.f32x2). E is stored in two parallel
// smem planes EA/EB, each [ipair][lane][4B*4]: a lane's 16B chunk sits at
// lane*16B (conflict-free LDS.128) and yields two packed (even-i, odd-i)
// operands. v2.u64 loads of the plain p array yield packed (p_2i, p_2i+1).
// No packing instructions anywhere in the inner loop.
//
// Sequences counting-sorted by length desc and grouped with variable
// multiplicity per warp: k=2 (len>=175), k=3 (len>=120), k=5 (rest).
// Small k shortens the serial critical path of long sequences; large k
// amortizes shared-memory E reads for short ones. Tasks (duration-sorted)
// are striped across CTAs with an SMSP-rotating snake.

#define NN 2048
#define TT 200
#define LL 129
#define LPAD 132
#define PSTR 136          // per-seq p buffer stride (floats), 16B aligned
#define FWD_CTAS 260
#define FWD_WARPS 4
#define MAXTASK 1040

__device__ __align__(16) float g_E[LL * LPAD];   // exp(transitions), padded
__device__ __align__(16) float g_Eend[LPAD];     // exp(end_transitions)
__device__ int   g_order[NN];
__device__ int   g_task[MAXTASK];                // base | (k<<12) | (cnt<<16)
__device__ int   g_ntask;
__device__ float g_num[NN];
__device__ float g_den[NN];

#define LOG2E 1.4426950408889634f
#define LN2F  0.6931471805599453f

__device__ __forceinline__ float ex2f(float x){ float r; asm("ex2.approx.ftz.f32 %0, %1;":"=f"(r):"f"(x)); return r; }
__device__ __forceinline__ float lg2f(float x){ float r; asm("lg2.approx.ftz.f32 %0, %1;":"=f"(r):"f"(x)); return r; }
__device__ __forceinline__ float rcpf(float x){ float r; asm("rcp.approx.ftz.f32 %0, %1;":"=f"(r):"f"(x)); return r; }

__device__ __forceinline__ unsigned smaddr(const void* p){
    unsigned r;
    asm("{.reg .u64 t; cvta.to.shared.u64 t, %1; cvt.u32.u64 %0, t;}":"=r"(r):"l"(p));
    return r;
}
// E loads: constant data, non-volatile (free to schedule/CSE)
__device__ __forceinline__ void ldsv2c(unsigned long long &a, unsigned long long &b, unsigned addr){
    asm("ld.shared.v2.u64 {%0,%1}, [%2];" : "=l"(a), "=l"(b) : "r"(addr));
}
// p loads: volatile (ordered against the volatile p stores below)
__device__ __forceinline__ void ldsv2p(unsigned long long &a, unsigned long long &b, unsigned addr){
    asm volatile("ld.shared.v2.u64 {%0,%1}, [%2];" : "=l"(a), "=l"(b) : "r"(addr));
}
__device__ __forceinline__ void sts4(unsigned addr, float a, float b, float c, float d){
    asm volatile("st.shared.v4.f32 [%0], {%1,%2,%3,%4};" :: "r"(addr),"f"(a),"f"(b),"f"(c),"f"(d) : "memory");
}
__device__ __forceinline__ void sts1(unsigned addr, float a){
    asm volatile("st.shared.f32 [%0], %1;" :: "r"(addr),"f"(a) : "memory");
}
__device__ __forceinline__ unsigned long long fma2(unsigned long long a, unsigned long long b, unsigned long long c){
    unsigned long long d;
    asm("fma.rn.f32x2 %0, %1, %2, %3;" : "=l"(d) : "l"(a), "l"(b), "l"(c));
    return d;
}
__device__ __forceinline__ float2 unpack2(unsigned long long v){
    float2 r; asm("mov.b64 {%0,%1}, %2;" : "=f"(r.x), "=f"(r.y) : "l"(v)); return r;
}

// ---------------------------------------------------------------------------
// Prep: E = exp(transitions) (col-padded with zeros), Eend = exp(end)
// ---------------------------------------------------------------------------
__global__ void prep_kernel(const float* __restrict__ trans,
                            const float* __restrict__ endt) {
    int idx = blockIdx.x * blockDim.x + threadIdx.x;
    if (idx < LL * LPAD) {
        int i = idx / LPAD, j = idx - i * LPAD;
        g_E[idx] = (j < LL) ? ex2f(trans[i * LL + j] * LOG2E) : 0.0f;
    }
    if (idx < LPAD) g_Eend[idx] = (idx < LL) ? ex2f(endt[idx] * LOG2E) : 0.0f;
}

// ---------------------------------------------------------------------------
// Counting sort by length desc + task schedule (bands k=2/3/5).
// ---------------------------------------------------------------------------
__global__ void sort_kernel(const int* __restrict__ lengths) {
    __shared__ int hist[256];
    __shared__ int c175, c120;
    int tid = threadIdx.x;
    for (int k = tid; k < 256; k += blockDim.x) hist[k] = 0;
    if (tid == 0) { c175 = 0; c120 = 0; }
    __syncthreads();
    for (int n = tid; n < NN; n += blockDim.x) {
        int l = lengths[n];
        atomicAdd(&hist[l], 1);
        if (l >= 175) atomicAdd(&c175, 1);
        if (l >= 120) atomicAdd(&c120, 1);
    }
    __syncthreads();
    if (tid == 0) {
        int run = 0;
        for (int l = 200; l >= 1; --l) { int c = hist[l]; hist[l] = run; run += c; }
    }
    __syncthreads();
    for (int n = tid; n < NN; n += blockDim.x) {
        int pos = atomicAdd(&hist[lengths[n]], 1);
        g_order[pos] = n;
    }
    __syncthreads();
    if (tid == 0) {
        int b2 = c175, b3 = c120;  // sorted desc => band boundaries are counts
        int t = 0;
        for (int i = 0; i < b2; i += 2) { int c = min(2, b2 - i); g_task[t++] = i | (2 << 12) | (c << 16); }
        for (int i = b2; i < b3; i += 3) { int c = min(3, b3 - i); g_task[t++] = i | (3 << 12) | (c << 16); }
        for (int i = b3; i < NN; i += 5) { int c = min(5, NN - i); g_task[t++] = i | (5 << 12) | (c << 16); }
        g_ntask = t;
    }
}

// ---------------------------------------------------------------------------
// Numerator: one warp per sequence.
// ---------------------------------------------------------------------------
__global__ void num_kernel(const float* __restrict__ score,
                           const float* __restrict__ trans,
                           const float* __restrict__ startt,
                           const float* __restrict__ endt,
                           const int* __restrict__ gold,
                           const int* __restrict__ lengths) {
    int w    = (blockIdx.x * blockDim.x + threadIdx.x) >> 5;
    int lane = threadIdx.x & 31;
    if (w >= NN) return;
    const int* g = gold + w * TT;
    int len = lengths[w];
    const float* sc = score + (size_t)w * TT * LL;
    float acc = 0.0f;
    for (int t = lane; t < len; t += 32) {
        int gt = __ldg(&g[t]);
        acc += __ldg(&sc[t * LL + gt]);
        if (t >= 1) {
            int gp = __ldg(&g[t - 1]);
            acc += __ldg(&trans[gp * LL + gt]);
        }
    }
    #pragma unroll
    for (int o = 16; o; o >>= 1) acc += __shfl_xor_sync(0xffffffffu, acc, o);
    if (lane == 0) g_num[w] = acc + startt[g[0]] + endt[g[len - 1]];
}

// ---------------------------------------------------------------------------
// Forward recurrence for one warp handling K sequences.
// Lane owns output columns j0..j0+3; accumulators are fp32x2 (even-i, odd-i)
// partials combined at the end of each step. Column 128 via butterfly.
// EA/EB planes: [ipair][lane][16B], lane stride 16B => conflict-free LDS.128.
// ---------------------------------------------------------------------------
template<int K>
__device__ __forceinline__ void run_group(
    int base, int cnt, int lane,
    const float* __restrict__ score, const float* __restrict__ startt,
    const int* __restrict__ lengths,
    const float* EA, const float* EB,
    const float* E128, const float* Ecol, const float* Een,
    float* pw)
{
    unsigned ea_a = smaddr(EA) + (unsigned)lane * 16u;
    unsigned eb_a = smaddr(EB) + (unsigned)lane * 16u;
    const float* sc[K]; float* pp[K]; unsigned ppa[K];
    int len[K], nid[K];
    #pragma unroll
    for (int s = 0; s < K; s++) {
        int n = g_order[base + ((s < cnt) ? s : 0)];
        nid[s] = n;
        len[s] = (s < cnt) ? lengths[n] : 1;
        sc[s]  = score + (size_t)n * TT * LL;
        pp[s]  = pw + s * PSTR;
        ppa[s] = smaddr(pp[s]);
    }
    int tmax = len[0];
    #pragma unroll
    for (int s = 1; s < K; s++) tmax = max(tmax, len[s]);
    int j0 = lane * 4;

    // init: p0[j] = exp(start[j] + score[n,0,j])
    {
        float4 st4 = *(const float4*)&startt[j0];
        float st128 = startt[128];
        #pragma unroll
        for (int s = 0; s < K; s++) {
            float4 a4 = *(const float4*)&sc[s][j0];   // row 0 is 16B aligned
            sts4(ppa[s] + (unsigned)j0 * 4u,
                 ex2f((st4.x + a4.x) * LOG2E), ex2f((st4.y + a4.y) * LOG2E),
                 ex2f((st4.z + a4.z) * LOG2E), ex2f((st4.w + a4.w) * LOG2E));
            if (lane == 0) sts1(ppa[s] + 128u * 4u, ex2f((st128 + sc[s][128]) * LOG2E));
        }
    }
    float c2[K];
    #pragma unroll
    for (int s = 0; s < K; s++) c2[s] = 0.0f;
    __syncwarp();

    for (int t = 1; t < tmax; ++t) {
        // emissions issued first (latency hidden under matvec)
        float em[K][4], em128[K];
        #pragma unroll
        for (int s = 0; s < K; s++) {
            const float* rp = sc[s] + t * LL;
            em[s][0] = __ldg(rp + j0);     em[s][1] = __ldg(rp + j0 + 1);
            em[s][2] = __ldg(rp + j0 + 2); em[s][3] = __ldg(rp + j0 + 3);
            em128[s] = __ldg(rp + 128);
        }

        unsigned long long acc[K][4];
        #pragma unroll
        for (int s = 0; s < K; s++) { acc[s][0] = 0ull; acc[s][1] = 0ull; acc[s][2] = 0ull; acc[s][3] = 0ull; }

        #pragma unroll 4
        for (int b = 0; b < 16; b++) {          // 8 i per block (4 ipairs)
            unsigned long long e[4][4];         // [ipair][j]
            #pragma unroll
            for (int q = 0; q < 4; q++) {
                unsigned off = (unsigned)((b * 4 + q) * 512);
                ldsv2c(e[q][0], e[q][1], ea_a + off);
                ldsv2c(e[q][2], e[q][3], eb_a + off);
            }
            #pragma unroll
            for (int s = 0; s < K; s++) {
                unsigned long long p01, p23, p45, p67;
                ldsv2p(p01, p23, ppa[s] + (unsigned)b * 32u);
                ldsv2p(p45, p67, ppa[s] + (unsigned)b * 32u + 16u);
                #pragma unroll
                for (int jj = 0; jj < 4; jj++) {
                    acc[s][jj] = fma2(e[0][jj], p01, acc[s][jj]);
                    acc[s][jj] = fma2(e[1][jj], p23, acc[s][jj]);
                    acc[s][jj] = fma2(e[2][jj], p45, acc[s][jj]);
                    acc[s][jj] = fma2(e[3][jj], p67, acc[s][jj]);
                }
            }
        }

        // i = 128 tail + combine halves + emission exp
        float4 e4 = *(const float4*)&E128[j0];
        float p128[K];
        #pragma unroll
        for (int s = 0; s < K; s++) p128[s] = pp[s][128];
        float u[K][4];
        #pragma unroll
        for (int s = 0; s < K; s++) {
            float2 h0 = unpack2(acc[s][0]), h1 = unpack2(acc[s][1]);
            float2 h2 = unpack2(acc[s][2]), h3 = unpack2(acc[s][3]);
            u[s][0] = (h0.x + h0.y + e4.x * p128[s]) * ex2f(em[s][0] * LOG2E);
            u[s][1] = (h1.x + h1.y + e4.y * p128[s]) * ex2f(em[s][1] * LOG2E);
            u[s][2] = (h2.x + h2.y + e4.z * p128[s]) * ex2f(em[s][2] * LOG2E);
            u[s][3] = (h3.x + h3.y + e4.w * p128[s]) * ex2f(em[s][3] * LOG2E);
        }

        // output column j = 128: i-parallel partials + butterfly
        float u128[K];
        {
            float ec0 = Ecol[lane], ec1 = Ecol[lane + 32], ec2 = Ecol[lane + 64], ec3 = Ecol[lane + 96];
            float ecl = Ecol[128];
            #pragma unroll
            for (int s = 0; s < K; s++) {
                float v = ec0 * pp[s][lane] + ec1 * pp[s][lane + 32]
                        + ec2 * pp[s][lane + 64] + ec3 * pp[s][lane + 96];
                if (lane == 0) v += ecl * p128[s];
                #pragma unroll
                for (int o = 16; o; o >>= 1) v += __shfl_xor_sync(0xffffffffu, v, o);
                u128[s] = v * ex2f(em128[s] * LOG2E);
            }
        }

        __syncwarp();   // all reads of old p done before any writes

        if ((t & 3) == 0) {
            #pragma unroll
            for (int s = 0; s < K; s++) {
                float tot = u[s][0] + u[s][1] + u[s][2] + u[s][3];
                if (lane == 0) tot += u128[s];
                #pragma unroll
                for (int o = 16; o; o >>= 1) tot += __shfl_xor_sync(0xffffffffu, tot, o);
                if (t < len[s]) {
                    float inv = rcpf(tot);
                    c2[s] += lg2f(tot);
                    sts4(ppa[s] + (unsigned)j0 * 4u,
                         u[s][0] * inv, u[s][1] * inv, u[s][2] * inv, u[s][3] * inv);
                    if (lane == 0) sts1(ppa[s] + 128u * 4u, u128[s] * inv);
                }
            }
        } else {
            #pragma unroll
            for (int s = 0; s < K; s++) {
                if (t < len[s]) {
                    sts4(ppa[s] + (unsigned)j0 * 4u, u[s][0], u[s][1], u[s][2], u[s][3]);
                    if (lane == 0) sts1(ppa[s] + 128u * 4u, u128[s]);
                }
            }
        }
        __syncwarp();
    }

    // finalize: log_den = ln2 * (c2 + log2(sum_j p[j]*Eend[j]))
    {
        float4 ee = *(const float4*)&Een[j0];
        #pragma unroll
        for (int s = 0; s < K; s++) {
            float4 pv = *(const float4*)&pp[s][j0];
            float v = ee.x * pv.x + ee.y * pv.y + ee.z * pv.z + ee.w * pv.w;
            if (lane == 0) v += Een[128] * pp[s][128];
            #pragma unroll
            for (int o = 16; o; o >>= 1) v += __shfl_xor_sync(0xffffffffu, v, o);
            if (lane == 0 && s < cnt) g_den[nid[s]] = LN2F * (c2[s] + lg2f(v));
        }
    }
}

// ---------------------------------------------------------------------------
__global__ void __launch_bounds__(FWD_WARPS * 32, 2)
fwd_kernel(const float* __restrict__ score,
           const float* __restrict__ startt,
           const int* __restrict__ lengths) {
    extern __shared__ float sm[];
    float* EA   = sm;                       // 64 ipairs * 32 lanes * 4 = 8192
    float* EB   = EA + 64 * 32 * 4;         // 8192
    float* E128 = EB + 64 * 32 * 4;         // LPAD  (E row 128)
    float* Ecol = E128 + LPAD;              // LPAD  (E column 128)
    float* Een  = Ecol + LPAD;              // LPAD
    float* pbuf = Een + LPAD;               // FWD_WARPS * 5 * PSTR

    int tid = threadIdx.x;
    // EA chunk (ip,lane) = {E[2ip][4l], E[2ip+1][4l], E[2ip][4l+1], E[2ip+1][4l+1]}
    // EB chunk           = same for columns 4l+2, 4l+3
    for (int k = tid; k < 64 * 32 * 4; k += blockDim.x) {
        int ip   = k >> 7;          // 128 floats per ipair row
        int rem  = k & 127;
        int lane = rem >> 2;
        int c    = rem & 3;
        int i    = 2 * ip + (c & 1);
        int j    = 4 * lane + (c >> 1);
        EA[k] = g_E[i * LPAD + j];
        EB[k] = g_E[i * LPAD + j + 2];
    }
    for (int k = tid; k < LPAD; k += blockDim.x) {
        E128[k] = g_E[128 * LPAD + k];
        Ecol[k] = (k < LL) ? g_E[k * LPAD + 128] : 0.0f;
        Een[k]  = g_Eend[k];
    }
    __syncthreads();

    int w = tid >> 5, lane = tid & 31;
    int cta = blockIdx.x;
    int band = (w + cta) & 3;               // rotate long tasks across SMSPs
    int r = band * FWD_CTAS + ((band & 1) ? (FWD_CTAS - 1 - cta) : cta);
    if (r >= g_ntask) return;

    int info = g_task[r];
    int base = info & 0xFFF, kk = (info >> 12) & 7, cnt = (info >> 16) & 7;
    float* pw = pbuf + w * (5 * PSTR);

    if (kk == 2)      run_group<2>(base, cnt, lane, score, startt, lengths, EA, EB, E128, Ecol, Een, pw);
    else if (kk == 3) run_group<3>(base, cnt, lane, score, startt, lengths, EA, EB, E128, Ecol, Een, pw);
    else              run_group<5>(base, cnt, lane, score, startt, lengths, EA, EB, E128, Ecol, Een, pw);
}

// ---------------------------------------------------------------------------
// Deterministic fixed-order reduction in double.
// ---------------------------------------------------------------------------
__global__ void red_kernel(float* __restrict__ out) {
    __shared__ double smd[1024];
    int tid = threadIdx.x;
    smd[tid] = (double)(g_num[tid] - g_den[tid]) +
               (double)(g_num[tid + 1024] - g_den[tid + 1024]);
    __syncthreads();
    #pragma unroll
    for (int s = 512; s > 0; s >>= 1) {
        if (tid < s) smd[tid] += smd[tid + s];
        __syncthreads();
    }
    if (tid == 0) out[0] = (float)smd[0];
}

// ---------------------------------------------------------------------------
extern "C" void kernel_launch(void* const* d_in, const int* in_sizes, int n_in,
                              void* d_out, int out_size) {
    const float* score   = (const float*)d_in[0];
    const float* trans   = (const float*)d_in[1];
    const float* startt  = (const float*)d_in[2];
    const float* endt    = (const float*)d_in[3];
    const int*   gold    = (const int*)d_in[4];
    const int*   lengths = (const int*)d_in[5];
    float* out = (float*)d_out;

    prep_kernel<<<(LL * LPAD + 255) / 256, 256>>>(trans, endt);
    sort_kernel<<<1, 256>>>(lengths);
    num_kernel<<<256, 256>>>(score, trans, startt, endt, gold, lengths);

    size_t smem = (size_t)(2 * 64 * 32 * 4 + 3 * LPAD + FWD_WARPS * 5 * PSTR) * sizeof(float);
    cudaFuncSetAttribute(fwd_kernel, cudaFuncAttributeMaxDynamicSharedMemorySize, (int)smem);
    fwd_kernel<<<FWD_CTAS, FWD_WARPS * 32, smem>>>(score, startt, lengths);

    red_kernel<<<1, 1024>>>(out);
}